// round 14
// baseline (speedup 1.0000x reference)
#include <cuda_runtime.h>
#include <cuda_fp16.h>
#include <cstdint>

// ---------------------------------------------------------------------------
// GATNet 2-layer GAT, N=50000, E=800000 (+self loops).
// GEMM1 = 3xFP16 tensor-core GEMM (Markidis split hh+hl+lh, f32 accum).
// Messages fp16; CSR built on side stream overlapped with GEMM1.
// agg kernels use manual 4-edge gather batching (MLP) — latency-bound fix.
// ---------------------------------------------------------------------------

#define NMAX 50000
#define EMAX 800000

__device__ __align__(16) __half2 g_xlh [NMAX * 32];  // xl as half2 pairs
__device__ __align__(16) float g_as1[NMAX * 8];
__device__ __align__(16) float g_ad1[NMAX * 8];
__device__ __align__(16) float g_hl2[NMAX * 16];
__device__ float g_as2[NMAX];
__device__ float g_ad2[NMAX];

__device__ int g_cnt [NMAX];   // zero at module load; re-zeroed by k_scatter
__device__ int g_inc [NMAX];
__device__ int g_bsum[64];
__device__ int g_rptr[NMAX + 1];
__device__ int g_rank[EMAX];
__device__ int g_col [EMAX];

__device__ __forceinline__ float leaky02(float a) { return fmaxf(a, 0.2f * a); }

__device__ __forceinline__ void split2(float x, float y,
                                       uint32_t& h, uint32_t& l) {
    __half hx = __float2half_rn(x), hy = __float2half_rn(y);
    __half lx = __float2half_rn(x - __half2float(hx));
    __half ly = __float2half_rn(y - __half2float(hy));
    __half2 hh = __halves2half2(hx, hy), ll = __halves2half2(lx, ly);
    h = *reinterpret_cast<uint32_t*>(&hh);
    l = *reinterpret_cast<uint32_t*>(&ll);
}

__device__ __forceinline__ void mma_f16(float4& c, uint32_t a0, uint32_t a1,
                                        uint32_t a2, uint32_t a3,
                                        uint32_t b0, uint32_t b1) {
    asm volatile(
        "mma.sync.aligned.m16n8k16.row.col.f32.f16.f16.f32 "
        "{%0,%1,%2,%3}, {%4,%5,%6,%7}, {%8,%9}, {%0,%1,%2,%3};\n"
        : "+f"(c.x), "+f"(c.y), "+f"(c.z), "+f"(c.w)
        : "r"(a0), "r"(a1), "r"(a2), "r"(a3), "r"(b0), "r"(b1));
}

// ----------------------------- CSR construction ----------------------------
// 8 edges per thread for MLP on the latency-bound atomic/gather chains.
__global__ void k_hist(const int* __restrict__ ei, int E) {
    int base = (blockIdx.x * blockDim.x + threadIdx.x) * 8;
    if (base >= E) return;
    int m = E - base; if (m > 8) m = 8;
    int d[8];
#pragma unroll
    for (int i = 0; i < 8; i++) if (i < m) d[i] = __ldg(ei + E + base + i);
#pragma unroll
    for (int i = 0; i < 8; i++)
        if (i < m) g_rank[base + i] = atomicAdd(&g_cnt[d[i]], 1);
}

__global__ __launch_bounds__(1024) void k_scan1(int N) {
    __shared__ int sw[32];
    int t = threadIdx.x, i = blockIdx.x * 1024 + t;
    int lane = t & 31, wid = t >> 5;
    int s = (i < N) ? g_cnt[i] : 0;
#pragma unroll
    for (int o = 1; o < 32; o <<= 1) {
        int u = __shfl_up_sync(0xffffffffu, s, o);
        if (lane >= o) s += u;
    }
    if (lane == 31) sw[wid] = s;
    __syncthreads();
    if (wid == 0) {
        int ws = sw[lane];
#pragma unroll
        for (int o = 1; o < 32; o <<= 1) {
            int u = __shfl_up_sync(0xffffffffu, ws, o);
            if (lane >= o) ws += u;
        }
        sw[lane] = ws;
    }
    __syncthreads();
    int incl = s + (wid ? sw[wid - 1] : 0);
    if (i < N) g_inc[i] = incl;
    if (t == 1023) g_bsum[blockIdx.x] = incl;
}

__global__ void k_scan3(int N, int E, int ntiles) {
    __shared__ int sh[64];
    int t = threadIdx.x;
    if (t < 32) {
        int a = (t < ntiles) ? g_bsum[t] : 0;
        int b = (t + 32 < ntiles) ? g_bsum[t + 32] : 0;
#pragma unroll
        for (int o = 1; o < 32; o <<= 1) {
            int u = __shfl_up_sync(0xffffffffu, a, o);
            if (t >= o) a += u;
        }
        int tot = __shfl_sync(0xffffffffu, a, 31);
#pragma unroll
        for (int o = 1; o < 32; o <<= 1) {
            int u = __shfl_up_sync(0xffffffffu, b, o);
            if (t >= o) b += u;
        }
        sh[t] = a;
        sh[t + 32] = b + tot;
    }
    __syncthreads();
    int i = blockIdx.x * blockDim.x + t;
    if (i < N) {
        int blk = i >> 10;
        int excl = blk ? sh[blk - 1] : 0;
        g_rptr[i] = g_inc[i] - g_cnt[i] + excl;
    }
    if (i == 0) g_rptr[N] = E;
}

__global__ void k_scatter(const int* __restrict__ ei, int E, int N) {
    int tid = blockIdx.x * blockDim.x + threadIdx.x;
    if (tid < N) g_cnt[tid] = 0;
    int base = tid * 8;
    if (base >= E) return;
    int m = E - base; if (m > 8) m = 8;
    int d[8], s[8], r[8], rp[8];
#pragma unroll
    for (int i = 0; i < 8; i++)
        if (i < m) { d[i] = __ldg(ei + E + base + i); s[i] = __ldg(ei + base + i); }
#pragma unroll
    for (int i = 0; i < 8; i++) if (i < m) r[i] = g_rank[base + i];
#pragma unroll
    for (int i = 0; i < 8; i++) if (i < m) rp[i] = g_rptr[d[i]];
#pragma unroll
    for (int i = 0; i < 8; i++) if (i < m) g_col[rp[i] + r[i]] = s[i];
}

// --------------- GEMM1 (3xFP16 MMA m16n8k16) + fused node1 logits ----------
__global__ __launch_bounds__(256) void k_gemm1(const float* __restrict__ X,
                                               const float* __restrict__ W,
                                               const float* __restrict__ att_s,
                                               const float* __restrict__ att_d,
                                               int N) {
    __shared__ __align__(16) __half2 sAh2[128][20];
    __shared__ __align__(16) __half2 sAl2[128][20];
    __shared__ __align__(16) __half2 sBh2[16][72];
    __shared__ __align__(16) __half2 sBl2[16][72];

    const int tid  = threadIdx.x;
    const int bm   = blockIdx.x * 128;
    const int warp = tid >> 5, lane = tid & 31;
    const int wm   = warp >> 1, wn = warp & 1;
    const int g    = lane >> 2, tig = lane & 3;

    const int ar  = tid >> 1, af4 = (tid & 1) * 4, ah2 = (tid & 1) * 8;
    const int bkk = tid >> 4, bq = (tid & 15) * 4;

    int axr = bm + ar;
    if (axr >= N) axr = N - 1;
    const float4* Xr = (const float4*)(X + (size_t)axr * 512);

    float4 acc[2][4];
#pragma unroll
    for (int i = 0; i < 2; i++)
#pragma unroll
        for (int j = 0; j < 4; j++) acc[i][j] = make_float4(0.f, 0.f, 0.f, 0.f);

    float4 ra[4], rb0, rb1;
#pragma unroll
    for (int i = 0; i < 4; i++) ra[i] = Xr[af4 + i];
    rb0 = *(const float4*)(W + (size_t)(2 * bkk) * 64 + bq);
    rb1 = *(const float4*)(W + (size_t)(2 * bkk + 1) * 64 + bq);

    for (int ks = 0; ks < 16; ks++) {
        uint32_t AH[8], AL[8];
#pragma unroll
        for (int i = 0; i < 4; i++) {
            split2(ra[i].x, ra[i].y, AH[2 * i],     AL[2 * i]);
            split2(ra[i].z, ra[i].w, AH[2 * i + 1], AL[2 * i + 1]);
        }
        *(uint4*)&sAh2[ar][ah2]     = *(uint4*)&AH[0];
        *(uint4*)&sAh2[ar][ah2 + 4] = *(uint4*)&AH[4];
        *(uint4*)&sAl2[ar][ah2]     = *(uint4*)&AL[0];
        *(uint4*)&sAl2[ar][ah2 + 4] = *(uint4*)&AL[4];
        uint32_t BH[4], BL[4];
        split2(rb0.x, rb1.x, BH[0], BL[0]);
        split2(rb0.y, rb1.y, BH[1], BL[1]);
        split2(rb0.z, rb1.z, BH[2], BL[2]);
        split2(rb0.w, rb1.w, BH[3], BL[3]);
        *(uint4*)&sBh2[bkk][bq] = *(uint4*)&BH[0];
        *(uint4*)&sBl2[bkk][bq] = *(uint4*)&BL[0];
        __syncthreads();

        if (ks < 15) {
            int k0 = (ks + 1) * 32;
#pragma unroll
            for (int i = 0; i < 4; i++) ra[i] = Xr[(k0 >> 2) + af4 + i];
            rb0 = *(const float4*)(W + (size_t)(k0 + 2 * bkk) * 64 + bq);
            rb1 = *(const float4*)(W + (size_t)(k0 + 2 * bkk + 1) * 64 + bq);
        }

#pragma unroll
        for (int ki = 0; ki < 2; ki++) {
            const int kc2 = ki * 8;
            uint32_t Ah[2][4], Al[2][4];
#pragma unroll
            for (int mt = 0; mt < 2; mt++) {
                const int r0 = wm * 32 + mt * 16 + g, r8 = r0 + 8;
                Ah[mt][0] = *(const uint32_t*)&sAh2[r0][kc2 + tig];
                Ah[mt][1] = *(const uint32_t*)&sAh2[r8][kc2 + tig];
                Ah[mt][2] = *(const uint32_t*)&sAh2[r0][kc2 + tig + 4];
                Ah[mt][3] = *(const uint32_t*)&sAh2[r8][kc2 + tig + 4];
                Al[mt][0] = *(const uint32_t*)&sAl2[r0][kc2 + tig];
                Al[mt][1] = *(const uint32_t*)&sAl2[r8][kc2 + tig];
                Al[mt][2] = *(const uint32_t*)&sAl2[r0][kc2 + tig + 4];
                Al[mt][3] = *(const uint32_t*)&sAl2[r8][kc2 + tig + 4];
            }
#pragma unroll
            for (int nt = 0; nt < 4; nt++) {
                const int nc = wn * 32 + nt * 8 + g;
                uint32_t bh0 = *(const uint32_t*)&sBh2[kc2 + tig][nc];
                uint32_t bh1 = *(const uint32_t*)&sBh2[kc2 + tig + 4][nc];
                uint32_t bl0 = *(const uint32_t*)&sBl2[kc2 + tig][nc];
                uint32_t bl1 = *(const uint32_t*)&sBl2[kc2 + tig + 4][nc];
#pragma unroll
                for (int mt = 0; mt < 2; mt++) {
                    mma_f16(acc[mt][nt], Al[mt][0], Al[mt][1], Al[mt][2],
                            Al[mt][3], bh0, bh1);
                    mma_f16(acc[mt][nt], Ah[mt][0], Ah[mt][1], Ah[mt][2],
                            Ah[mt][3], bl0, bl1);
                    mma_f16(acc[mt][nt], Ah[mt][0], Ah[mt][1], Ah[mt][2],
                            Ah[mt][3], bh0, bh1);
                }
            }
        }
        __syncthreads();
    }

#pragma unroll
    for (int mt = 0; mt < 2; mt++) {
        const int row0 = bm + wm * 32 + mt * 16 + g;
        const int row1 = row0 + 8;
        float s0a[4], s1a[4], d0a[4], d1a[4];
#pragma unroll
        for (int nt = 0; nt < 4; nt++) {
            const int h = wn * 4 + nt;
            const int colh = h * 4 + tig;
            float4 a = acc[mt][nt];
            if (row0 < N)
                g_xlh[(size_t)row0 * 32 + colh] = __floats2half2_rn(a.x, a.y);
            if (row1 < N)
                g_xlh[(size_t)row1 * 32 + colh] = __floats2half2_rn(a.z, a.w);

            float2 asv = make_float2(__ldg(att_s + h * 8 + 2 * tig),
                                     __ldg(att_s + h * 8 + 2 * tig + 1));
            float2 adv = make_float2(__ldg(att_d + h * 8 + 2 * tig),
                                     __ldg(att_d + h * 8 + 2 * tig + 1));
            float s0 = a.x * asv.x + a.y * asv.y;
            float s1 = a.z * asv.x + a.w * asv.y;
            float d0 = a.x * adv.x + a.y * adv.y;
            float d1 = a.z * adv.x + a.w * adv.y;
#pragma unroll
            for (int off = 1; off < 4; off <<= 1) {
                s0 += __shfl_xor_sync(0xffffffffu, s0, off);
                s1 += __shfl_xor_sync(0xffffffffu, s1, off);
                d0 += __shfl_xor_sync(0xffffffffu, d0, off);
                d1 += __shfl_xor_sync(0xffffffffu, d1, off);
            }
            s0a[nt] = s0; s1a[nt] = s1; d0a[nt] = d0; d1a[nt] = d1;
        }
        if (tig == 0) {
            if (row0 < N) {
                *(float4*)&g_as1[row0 * 8 + wn * 4] =
                    make_float4(s0a[0], s0a[1], s0a[2], s0a[3]);
                *(float4*)&g_ad1[row0 * 8 + wn * 4] =
                    make_float4(d0a[0], d0a[1], d0a[2], d0a[3]);
            }
            if (row1 < N) {
                *(float4*)&g_as1[row1 * 8 + wn * 4] =
                    make_float4(s1a[0], s1a[1], s1a[2], s1a[3]);
                *(float4*)&g_ad1[row1 * 8 + wn * 4] =
                    make_float4(d1a[0], d1a[1], d1a[2], d1a[3]);
            }
        }
    }
}

// ---- layer1 aggregation + bias + layer2 GEMM + layer2 logits (fused) ------
// Warp per node; edges processed in batches of 4 with pre-issued gathers.
__global__ __launch_bounds__(256) void k_agg1(const float* __restrict__ b1,
                                              const float* __restrict__ W2,
                                              const float* __restrict__ atts2,
                                              const float* __restrict__ attd2,
                                              int N) {
    __shared__ float sh[8][64];
    int warp = (blockIdx.x * blockDim.x + threadIdx.x) >> 5;
    int wl = (threadIdx.x >> 5);
    int lane = threadIdx.x & 31;
    if (warp >= N) return;
    const int d = warp;
    const int h = lane >> 2;
    const float ad = g_ad1[d * 8 + h];

    float w = __expf(leaky02(g_as1[d * 8 + h] + ad));
    float2 v = __half22float2(g_xlh[(size_t)d * 32 + lane]);
    float nx = w * v.x, ny = w * v.y;
    float den = ((lane & 3) == 0) ? w : 0.f;

    const int r1 = g_rptr[d + 1];
    int e = g_rptr[d];
    for (; e + 4 <= r1; e += 4) {
        int s0 = g_col[e], s1 = g_col[e + 1], s2 = g_col[e + 2], s3 = g_col[e + 3];
        float a0 = g_as1[s0 * 8 + h];
        float a1 = g_as1[s1 * 8 + h];
        float a2 = g_as1[s2 * 8 + h];
        float a3 = g_as1[s3 * 8 + h];
        float2 x0 = __half22float2(g_xlh[(size_t)s0 * 32 + lane]);
        float2 x1 = __half22float2(g_xlh[(size_t)s1 * 32 + lane]);
        float2 x2 = __half22float2(g_xlh[(size_t)s2 * 32 + lane]);
        float2 x3 = __half22float2(g_xlh[(size_t)s3 * 32 + lane]);
        float w0 = __expf(leaky02(a0 + ad));
        float w1 = __expf(leaky02(a1 + ad));
        float w2 = __expf(leaky02(a2 + ad));
        float w3 = __expf(leaky02(a3 + ad));
        nx += w0 * x0.x; ny += w0 * x0.y;
        nx += w1 * x1.x; ny += w1 * x1.y;
        nx += w2 * x2.x; ny += w2 * x2.y;
        nx += w3 * x3.x; ny += w3 * x3.y;
        if ((lane & 3) == 0) den += w0 + w1 + w2 + w3;
    }
    for (; e < r1; e++) {
        int s = g_col[e];
        float we = __expf(leaky02(g_as1[s * 8 + h] + ad));
        float2 xs = __half22float2(g_xlh[(size_t)s * 32 + lane]);
        nx += we * xs.x;
        ny += we * xs.y;
        if ((lane & 3) == 0) den += we;
    }
    float dfull = __shfl_sync(0xffffffffu, den, lane & ~3) + 1e-16f;
    float inv = 1.f / dfull;

    sh[wl][lane * 2]     = nx * inv + __ldg(b1 + lane * 2);
    sh[wl][lane * 2 + 1] = ny * inv + __ldg(b1 + lane * 2 + 1);
    __syncwarp();

    const int c = lane & 15;
    const int jb = (lane >> 4) * 32;
    float y = 0.f;
#pragma unroll
    for (int j2 = 0; j2 < 32; j2++) {
        int j = jb + j2;
        y += sh[wl][j] * __ldg(W2 + j * 16 + c);
    }
    y += __shfl_xor_sync(0xffffffffu, y, 16);

    if (lane < 16) g_hl2[(size_t)d * 16 + c] = y;

    float pa = y * __ldg(atts2 + c);
    float pd = y * __ldg(attd2 + c);
#pragma unroll
    for (int off = 8; off >= 1; off >>= 1) {
        pa += __shfl_xor_sync(0xffffffffu, pa, off);
        pd += __shfl_xor_sync(0xffffffffu, pd, off);
    }
    if (lane == 0) {
        g_as2[d] = pa;
        g_ad2[d] = pd;
    }
}

// ------ layer2 aggregation + bias + elu + log_softmax (16 lanes/node) ------
__global__ __launch_bounds__(256) void k_agg2(const float* __restrict__ b2,
                                              float* __restrict__ out, int N) {
    int gid = (blockIdx.x * blockDim.x + threadIdx.x) >> 4;
    int c = threadIdx.x & 15;
    bool valid = gid < N;
    const int d = valid ? gid : 0;
    const float ad = g_ad2[d];

    float w = __expf(leaky02(g_as2[d] + ad));
    float num = w * g_hl2[(size_t)d * 16 + c];
    float den = w;

    const int r1 = g_rptr[d + 1];
    int e = g_rptr[d];
    for (; e + 4 <= r1; e += 4) {
        int s0 = g_col[e], s1 = g_col[e + 1], s2 = g_col[e + 2], s3 = g_col[e + 3];
        float a0 = g_as2[s0], a1 = g_as2[s1], a2 = g_as2[s2], a3 = g_as2[s3];
        float h0 = g_hl2[(size_t)s0 * 16 + c];
        float h1 = g_hl2[(size_t)s1 * 16 + c];
        float h2 = g_hl2[(size_t)s2 * 16 + c];
        float h3 = g_hl2[(size_t)s3 * 16 + c];
        float w0 = __expf(leaky02(a0 + ad));
        float w1 = __expf(leaky02(a1 + ad));
        float w2 = __expf(leaky02(a2 + ad));
        float w3 = __expf(leaky02(a3 + ad));
        num += w0 * h0; num += w1 * h1; num += w2 * h2; num += w3 * h3;
        den += w0 + w1 + w2 + w3;
    }
    for (; e < r1; e++) {
        int s = g_col[e];
        float we = __expf(leaky02(g_as2[s] + ad));
        num += we * g_hl2[(size_t)s * 16 + c];
        den += we;
    }
    float x = num / (den + 1e-16f) + __ldg(b2 + c);
    x = (x > 0.f) ? x : (__expf(x) - 1.f);

    float m = x;
#pragma unroll
    for (int off = 1; off < 16; off <<= 1)
        m = fmaxf(m, __shfl_xor_sync(0xffffffffu, m, off));
    float ssum = __expf(x - m);
#pragma unroll
    for (int off = 1; off < 16; off <<= 1)
        ssum += __shfl_xor_sync(0xffffffffu, ssum, off);
    if (valid) out[(size_t)d * 16 + c] = x - m - __logf(ssum);
}

// ---------------------------------------------------------------------------
extern "C" void kernel_launch(void* const* d_in, const int* in_sizes, int n_in,
                              void* d_out, int out_size) {
    const float* x     = (const float*)d_in[0];
    const int*   ei    = (const int*)d_in[1];
    const float* W1    = (const float*)d_in[2];
    const float* atts1 = (const float*)d_in[3];
    const float* attd1 = (const float*)d_in[4];
    const float* b1    = (const float*)d_in[5];
    const float* W2    = (const float*)d_in[6];
    const float* atts2 = (const float*)d_in[7];
    const float* attd2 = (const float*)d_in[8];
    const float* b2    = (const float*)d_in[9];
    float* out = (float*)d_out;

    const int N = in_sizes[0] / 512;
    const int E = in_sizes[1] / 2;
    const int ntiles = (N + 1023) >> 10;

    static cudaStream_t s_csr = nullptr;
    static cudaEvent_t ev_fork = nullptr, ev_join = nullptr;
    if (!s_csr) {
        cudaStreamCreateWithFlags(&s_csr, cudaStreamNonBlocking);
        cudaEventCreateWithFlags(&ev_fork, cudaEventDisableTiming);
        cudaEventCreateWithFlags(&ev_join, cudaEventDisableTiming);
    }

    // fork: CSR build on s_csr, GEMM1 on the main stream
    cudaEventRecord(ev_fork, 0);
    cudaStreamWaitEvent(s_csr, ev_fork, 0);

    k_hist<<<(E / 8 + 255) / 256, 256, 0, s_csr>>>(ei, E);
    k_scan1<<<ntiles, 1024, 0, s_csr>>>(N);
    k_scan3<<<(N + 255) / 256, 256, 0, s_csr>>>(N, E, ntiles);
    k_scatter<<<(E / 8 + 255) / 256, 256, 0, s_csr>>>(ei, E, N);
    cudaEventRecord(ev_join, s_csr);

    k_gemm1<<<(N + 127) / 128, 256>>>(x, W1, atts1, attd1, N);

    // join: aggregation needs both CSR and GEMM1
    cudaStreamWaitEvent(0, ev_join, 0);

    k_agg1<<<(N * 32 + 255) / 256, 256>>>(b1, W2, atts2, attd2, N);
    k_agg2<<<(N * 16 + 255) / 256, 256>>>(b2, out, N);
}

// round 15
// speedup vs baseline: 1.0653x; 1.0653x over previous
#include <cuda_runtime.h>
#include <cuda_fp16.h>
#include <cstdint>

// ---------------------------------------------------------------------------
// GATNet 2-layer GAT, N=50000, E=800000 (+self loops).
// GEMM1 = 2xFP16 tensor-core GEMM (A split hi+lo, B hi only; f32 accum;
// residual A*Blo ~1.4e-4 rel, well under the 1e-3 gate).
// Messages fp16; CSR built on side stream overlapped with GEMM1.
// agg1 fuses layer-1 aggregation + bias + layer-2 GEMM + layer-2 logits.
// ---------------------------------------------------------------------------

#define NMAX 50000
#define EMAX 800000

__device__ __align__(16) __half2 g_xlh [NMAX * 32];  // xl as half2 pairs
__device__ __align__(16) float g_as1[NMAX * 8];
__device__ __align__(16) float g_ad1[NMAX * 8];
__device__ __align__(16) float g_hl2[NMAX * 16];
__device__ float g_as2[NMAX];
__device__ float g_ad2[NMAX];

__device__ int g_cnt [NMAX];   // zero at module load; re-zeroed by k_scatter
__device__ int g_inc [NMAX];
__device__ int g_bsum[64];
__device__ int g_rptr[NMAX + 1];
__device__ int g_rank[EMAX];
__device__ int g_col [EMAX];

__device__ __forceinline__ float leaky02(float a) { return fmaxf(a, 0.2f * a); }

// full split: (x,y) -> hi half2 + lo half2 (packed u32)
__device__ __forceinline__ void split2(float x, float y,
                                       uint32_t& h, uint32_t& l) {
    __half hx = __float2half_rn(x), hy = __float2half_rn(y);
    __half lx = __float2half_rn(x - __half2float(hx));
    __half ly = __float2half_rn(y - __half2float(hy));
    __half2 hh = __halves2half2(hx, hy), ll = __halves2half2(lx, ly);
    h = *reinterpret_cast<uint32_t*>(&hh);
    l = *reinterpret_cast<uint32_t*>(&ll);
}

// hi-only pack: (x,y) -> half2 (packed u32)
__device__ __forceinline__ uint32_t pack2h(float x, float y) {
    __half2 hh = __floats2half2_rn(x, y);
    return *reinterpret_cast<uint32_t*>(&hh);
}

__device__ __forceinline__ void mma_f16(float4& c, uint32_t a0, uint32_t a1,
                                        uint32_t a2, uint32_t a3,
                                        uint32_t b0, uint32_t b1) {
    asm volatile(
        "mma.sync.aligned.m16n8k16.row.col.f32.f16.f16.f32 "
        "{%0,%1,%2,%3}, {%4,%5,%6,%7}, {%8,%9}, {%0,%1,%2,%3};\n"
        : "+f"(c.x), "+f"(c.y), "+f"(c.z), "+f"(c.w)
        : "r"(a0), "r"(a1), "r"(a2), "r"(a3), "r"(b0), "r"(b1));
}

// ----------------------------- CSR construction ----------------------------
__global__ void k_hist(const int* __restrict__ ei, int E) {
    int base = (blockIdx.x * blockDim.x + threadIdx.x) * 4;
    if (base >= E) return;
    int m = E - base; if (m > 4) m = 4;
    int d[4];
#pragma unroll
    for (int i = 0; i < 4; i++) if (i < m) d[i] = ei[E + base + i];
#pragma unroll
    for (int i = 0; i < 4; i++)
        if (i < m) g_rank[base + i] = atomicAdd(&g_cnt[d[i]], 1);
}

__global__ __launch_bounds__(1024) void k_scan1(int N) {
    __shared__ int sw[32];
    int t = threadIdx.x, i = blockIdx.x * 1024 + t;
    int lane = t & 31, wid = t >> 5;
    int s = (i < N) ? g_cnt[i] : 0;
#pragma unroll
    for (int o = 1; o < 32; o <<= 1) {
        int u = __shfl_up_sync(0xffffffffu, s, o);
        if (lane >= o) s += u;
    }
    if (lane == 31) sw[wid] = s;
    __syncthreads();
    if (wid == 0) {
        int ws = sw[lane];
#pragma unroll
        for (int o = 1; o < 32; o <<= 1) {
            int u = __shfl_up_sync(0xffffffffu, ws, o);
            if (lane >= o) ws += u;
        }
        sw[lane] = ws;
    }
    __syncthreads();
    int incl = s + (wid ? sw[wid - 1] : 0);
    if (i < N) g_inc[i] = incl;
    if (t == 1023) g_bsum[blockIdx.x] = incl;
}

__global__ void k_scan3(int N, int E, int ntiles) {
    __shared__ int sh[64];
    int t = threadIdx.x;
    if (t < 32) {
        int a = (t < ntiles) ? g_bsum[t] : 0;
        int b = (t + 32 < ntiles) ? g_bsum[t + 32] : 0;
#pragma unroll
        for (int o = 1; o < 32; o <<= 1) {
            int u = __shfl_up_sync(0xffffffffu, a, o);
            if (t >= o) a += u;
        }
        int tot = __shfl_sync(0xffffffffu, a, 31);
#pragma unroll
        for (int o = 1; o < 32; o <<= 1) {
            int u = __shfl_up_sync(0xffffffffu, b, o);
            if (t >= o) b += u;
        }
        sh[t] = a;
        sh[t + 32] = b + tot;
    }
    __syncthreads();
    int i = blockIdx.x * blockDim.x + t;
    if (i < N) {
        int blk = i >> 10;
        int excl = blk ? sh[blk - 1] : 0;
        g_rptr[i] = g_inc[i] - g_cnt[i] + excl;
    }
    if (i == 0) g_rptr[N] = E;
}

__global__ void k_scatter(const int* __restrict__ ei, int E, int N) {
    int tid = blockIdx.x * blockDim.x + threadIdx.x;
    if (tid < N) g_cnt[tid] = 0;
    int base = tid * 4;
    if (base >= E) return;
    int m = E - base; if (m > 4) m = 4;
    int d[4], s[4], r[4], rp[4];
#pragma unroll
    for (int i = 0; i < 4; i++)
        if (i < m) { d[i] = ei[E + base + i]; s[i] = ei[base + i]; }
#pragma unroll
    for (int i = 0; i < 4; i++) if (i < m) r[i] = g_rank[base + i];
#pragma unroll
    for (int i = 0; i < 4; i++) if (i < m) rp[i] = g_rptr[d[i]];
#pragma unroll
    for (int i = 0; i < 4; i++) if (i < m) g_col[rp[i] + r[i]] = s[i];
}

// ----------- GEMM1 (2xFP16 MMA m16n8k16, B hi-only) + node1 logits ---------
// xl = X @ W1, block tile 128x64, BK=32, 8 warps = 4(M) x 2(N), warp 32x32.
__global__ __launch_bounds__(256) void k_gemm1(const float* __restrict__ X,
                                               const float* __restrict__ W,
                                               const float* __restrict__ att_s,
                                               const float* __restrict__ att_d,
                                               int N) {
    __shared__ __align__(16) __half2 sAh2[128][20];
    __shared__ __align__(16) __half2 sAl2[128][20];
    __shared__ __align__(16) __half2 sBh2[16][72];

    const int tid  = threadIdx.x;
    const int bm   = blockIdx.x * 128;
    const int warp = tid >> 5, lane = tid & 31;
    const int wm   = warp >> 1, wn = warp & 1;
    const int g    = lane >> 2, tig = lane & 3;

    const int ar  = tid >> 1, af4 = (tid & 1) * 4, ah2 = (tid & 1) * 8;
    const int bkk = tid >> 4, bq = (tid & 15) * 4;

    int axr = bm + ar;
    if (axr >= N) axr = N - 1;   // clamp; stores guarded
    const float4* Xr = (const float4*)(X + (size_t)axr * 512);

    float4 acc[2][4];
#pragma unroll
    for (int i = 0; i < 2; i++)
#pragma unroll
        for (int j = 0; j < 4; j++) acc[i][j] = make_float4(0.f, 0.f, 0.f, 0.f);

    float4 ra[4], rb0, rb1;
#pragma unroll
    for (int i = 0; i < 4; i++) ra[i] = Xr[af4 + i];
    rb0 = *(const float4*)(W + (size_t)(2 * bkk) * 64 + bq);
    rb1 = *(const float4*)(W + (size_t)(2 * bkk + 1) * 64 + bq);

    for (int ks = 0; ks < 16; ks++) {
        uint32_t AH[8], AL[8];
#pragma unroll
        for (int i = 0; i < 4; i++) {
            split2(ra[i].x, ra[i].y, AH[2 * i],     AL[2 * i]);
            split2(ra[i].z, ra[i].w, AH[2 * i + 1], AL[2 * i + 1]);
        }
        *(uint4*)&sAh2[ar][ah2]     = *(uint4*)&AH[0];
        *(uint4*)&sAh2[ar][ah2 + 4] = *(uint4*)&AH[4];
        *(uint4*)&sAl2[ar][ah2]     = *(uint4*)&AL[0];
        *(uint4*)&sAl2[ar][ah2 + 4] = *(uint4*)&AL[4];
        uint32_t BH[4];
        BH[0] = pack2h(rb0.x, rb1.x);
        BH[1] = pack2h(rb0.y, rb1.y);
        BH[2] = pack2h(rb0.z, rb1.z);
        BH[3] = pack2h(rb0.w, rb1.w);
        *(uint4*)&sBh2[bkk][bq] = *(uint4*)&BH[0];
        __syncthreads();

        if (ks < 15) {
            int k0 = (ks + 1) * 32;
#pragma unroll
            for (int i = 0; i < 4; i++) ra[i] = Xr[(k0 >> 2) + af4 + i];
            rb0 = *(const float4*)(W + (size_t)(k0 + 2 * bkk) * 64 + bq);
            rb1 = *(const float4*)(W + (size_t)(k0 + 2 * bkk + 1) * 64 + bq);
        }

#pragma unroll
        for (int ki = 0; ki < 2; ki++) {
            const int kc2 = ki * 8;
            uint32_t Ah[2][4], Al[2][4];
#pragma unroll
            for (int mt = 0; mt < 2; mt++) {
                const int r0 = wm * 32 + mt * 16 + g, r8 = r0 + 8;
                Ah[mt][0] = *(const uint32_t*)&sAh2[r0][kc2 + tig];
                Ah[mt][1] = *(const uint32_t*)&sAh2[r8][kc2 + tig];
                Ah[mt][2] = *(const uint32_t*)&sAh2[r0][kc2 + tig + 4];
                Ah[mt][3] = *(const uint32_t*)&sAh2[r8][kc2 + tig + 4];
                Al[mt][0] = *(const uint32_t*)&sAl2[r0][kc2 + tig];
                Al[mt][1] = *(const uint32_t*)&sAl2[r8][kc2 + tig];
                Al[mt][2] = *(const uint32_t*)&sAl2[r0][kc2 + tig + 4];
                Al[mt][3] = *(const uint32_t*)&sAl2[r8][kc2 + tig + 4];
            }
#pragma unroll
            for (int nt = 0; nt < 4; nt++) {
                const int nc = wn * 32 + nt * 8 + g;
                uint32_t bh0 = *(const uint32_t*)&sBh2[kc2 + tig][nc];
                uint32_t bh1 = *(const uint32_t*)&sBh2[kc2 + tig + 4][nc];
#pragma unroll
                for (int mt = 0; mt < 2; mt++) {
                    mma_f16(acc[mt][nt], Al[mt][0], Al[mt][1], Al[mt][2],
                            Al[mt][3], bh0, bh1);
                    mma_f16(acc[mt][nt], Ah[mt][0], Ah[mt][1], Ah[mt][2],
                            Ah[mt][3], bh0, bh1);
                }
            }
        }
        __syncthreads();
    }

#pragma unroll
    for (int mt = 0; mt < 2; mt++) {
        const int row0 = bm + wm * 32 + mt * 16 + g;
        const int row1 = row0 + 8;
        float s0a[4], s1a[4], d0a[4], d1a[4];
#pragma unroll
        for (int nt = 0; nt < 4; nt++) {
            const int h = wn * 4 + nt;
            const int colh = h * 4 + tig;
            float4 a = acc[mt][nt];
            if (row0 < N)
                g_xlh[(size_t)row0 * 32 + colh] = __floats2half2_rn(a.x, a.y);
            if (row1 < N)
                g_xlh[(size_t)row1 * 32 + colh] = __floats2half2_rn(a.z, a.w);

            float2 asv = make_float2(__ldg(att_s + h * 8 + 2 * tig),
                                     __ldg(att_s + h * 8 + 2 * tig + 1));
            float2 adv = make_float2(__ldg(att_d + h * 8 + 2 * tig),
                                     __ldg(att_d + h * 8 + 2 * tig + 1));
            float s0 = a.x * asv.x + a.y * asv.y;
            float s1 = a.z * asv.x + a.w * asv.y;
            float d0 = a.x * adv.x + a.y * adv.y;
            float d1 = a.z * adv.x + a.w * adv.y;
#pragma unroll
            for (int off = 1; off < 4; off <<= 1) {
                s0 += __shfl_xor_sync(0xffffffffu, s0, off);
                s1 += __shfl_xor_sync(0xffffffffu, s1, off);
                d0 += __shfl_xor_sync(0xffffffffu, d0, off);
                d1 += __shfl_xor_sync(0xffffffffu, d1, off);
            }
            s0a[nt] = s0; s1a[nt] = s1; d0a[nt] = d0; d1a[nt] = d1;
        }
        if (tig == 0) {
            if (row0 < N) {
                *(float4*)&g_as1[row0 * 8 + wn * 4] =
                    make_float4(s0a[0], s0a[1], s0a[2], s0a[3]);
                *(float4*)&g_ad1[row0 * 8 + wn * 4] =
                    make_float4(d0a[0], d0a[1], d0a[2], d0a[3]);
            }
            if (row1 < N) {
                *(float4*)&g_as1[row1 * 8 + wn * 4] =
                    make_float4(s1a[0], s1a[1], s1a[2], s1a[3]);
                *(float4*)&g_ad1[row1 * 8 + wn * 4] =
                    make_float4(d1a[0], d1a[1], d1a[2], d1a[3]);
            }
        }
    }
}

// ---- layer1 aggregation + bias + layer2 GEMM + layer2 logits (fused) ------
__global__ __launch_bounds__(256) void k_agg1(const float* __restrict__ b1,
                                              const float* __restrict__ W2,
                                              const float* __restrict__ atts2,
                                              const float* __restrict__ attd2,
                                              int N) {
    __shared__ float sh[8][64];
    int warp = (blockIdx.x * blockDim.x + threadIdx.x) >> 5;
    int wl = (threadIdx.x >> 5);
    int lane = threadIdx.x & 31;
    if (warp >= N) return;
    const int d = warp;
    const int h = lane >> 2;
    const float ad = g_ad1[d * 8 + h];

    float w = __expf(leaky02(g_as1[d * 8 + h] + ad));
    float2 v = __half22float2(g_xlh[(size_t)d * 32 + lane]);
    float nx = w * v.x, ny = w * v.y;
    float den = ((lane & 3) == 0) ? w : 0.f;

    const int e1 = g_rptr[d + 1];
#pragma unroll 4
    for (int e = g_rptr[d]; e < e1; e++) {
        int s = g_col[e];
        float we = __expf(leaky02(g_as1[s * 8 + h] + ad));
        float2 xs = __half22float2(g_xlh[(size_t)s * 32 + lane]);
        nx += we * xs.x;
        ny += we * xs.y;
        if ((lane & 3) == 0) den += we;
    }
    float dfull = __shfl_sync(0xffffffffu, den, lane & ~3) + 1e-16f;
    float inv = 1.f / dfull;

    sh[wl][lane * 2]     = nx * inv + __ldg(b1 + lane * 2);
    sh[wl][lane * 2 + 1] = ny * inv + __ldg(b1 + lane * 2 + 1);
    __syncwarp();

    const int c = lane & 15;
    const int jb = (lane >> 4) * 32;
    float y = 0.f;
#pragma unroll
    for (int j2 = 0; j2 < 32; j2++) {
        int j = jb + j2;
        y += sh[wl][j] * __ldg(W2 + j * 16 + c);
    }
    y += __shfl_xor_sync(0xffffffffu, y, 16);

    if (lane < 16) g_hl2[(size_t)d * 16 + c] = y;

    float pa = y * __ldg(atts2 + c);
    float pd = y * __ldg(attd2 + c);
#pragma unroll
    for (int off = 8; off >= 1; off >>= 1) {
        pa += __shfl_xor_sync(0xffffffffu, pa, off);
        pd += __shfl_xor_sync(0xffffffffu, pd, off);
    }
    if (lane == 0) {
        g_as2[d] = pa;
        g_ad2[d] = pd;
    }
}

// ------ layer2 aggregation + bias + elu + log_softmax (16 lanes/node) ------
__global__ __launch_bounds__(256) void k_agg2(const float* __restrict__ b2,
                                              float* __restrict__ out, int N) {
    int gid = (blockIdx.x * blockDim.x + threadIdx.x) >> 4;
    int c = threadIdx.x & 15;
    bool valid = gid < N;
    const int d = valid ? gid : 0;
    const float ad = g_ad2[d];

    float w = __expf(leaky02(g_as2[d] + ad));
    float num = w * g_hl2[(size_t)d * 16 + c];
    float den = w;

    const int e1 = g_rptr[d + 1];
#pragma unroll 4
    for (int e = g_rptr[d]; e < e1; e++) {
        int s = g_col[e];
        float we = __expf(leaky02(g_as2[s] + ad));
        num += we * g_hl2[(size_t)s * 16 + c];
        den += we;
    }
    float x = num / (den + 1e-16f) + __ldg(b2 + c);
    x = (x > 0.f) ? x : (__expf(x) - 1.f);

    float m = x;
#pragma unroll
    for (int off = 1; off < 16; off <<= 1)
        m = fmaxf(m, __shfl_xor_sync(0xffffffffu, m, off));
    float ssum = __expf(x - m);
#pragma unroll
    for (int off = 1; off < 16; off <<= 1)
        ssum += __shfl_xor_sync(0xffffffffu, ssum, off);
    if (valid) out[(size_t)d * 16 + c] = x - m - __logf(ssum);
}

// ---------------------------------------------------------------------------
extern "C" void kernel_launch(void* const* d_in, const int* in_sizes, int n_in,
                              void* d_out, int out_size) {
    const float* x     = (const float*)d_in[0];
    const int*   ei    = (const int*)d_in[1];
    const float* W1    = (const float*)d_in[2];
    const float* atts1 = (const float*)d_in[3];
    const float* attd1 = (const float*)d_in[4];
    const float* b1    = (const float*)d_in[5];
    const float* W2    = (const float*)d_in[6];
    const float* atts2 = (const float*)d_in[7];
    const float* attd2 = (const float*)d_in[8];
    const float* b2    = (const float*)d_in[9];
    float* out = (float*)d_out;

    const int N = in_sizes[0] / 512;
    const int E = in_sizes[1] / 2;
    const int ntiles = (N + 1023) >> 10;

    static cudaStream_t s_csr = nullptr;
    static cudaEvent_t ev_fork = nullptr, ev_join = nullptr;
    if (!s_csr) {
        cudaStreamCreateWithFlags(&s_csr, cudaStreamNonBlocking);
        cudaEventCreateWithFlags(&ev_fork, cudaEventDisableTiming);
        cudaEventCreateWithFlags(&ev_join, cudaEventDisableTiming);
    }

    // fork: CSR build on s_csr, GEMM1 on the main stream
    cudaEventRecord(ev_fork, 0);
    cudaStreamWaitEvent(s_csr, ev_fork, 0);

    k_hist<<<(E / 4 + 255) / 256, 256, 0, s_csr>>>(ei, E);
    k_scan1<<<ntiles, 1024, 0, s_csr>>>(N);
    k_scan3<<<(N + 255) / 256, 256, 0, s_csr>>>(N, E, ntiles);
    k_scatter<<<(E / 4 + 255) / 256, 256, 0, s_csr>>>(ei, E, N);
    cudaEventRecord(ev_join, s_csr);

    k_gemm1<<<(N + 127) / 128, 256>>>(x, W1, atts1, attd1, N);

    // join: aggregation needs both CSR and GEMM1
    cudaStreamWaitEvent(0, ev_join, 0);

    k_agg1<<<(N * 32 + 255) / 256, 256>>>(b1, W2, atts2, attd2, N);
    k_agg2<<<(N * 16 + 255) / 256, 256>>>(b2, out, N);
}

// round 16
// speedup vs baseline: 1.1012x; 1.0337x over previous
#include <cuda_runtime.h>
#include <cuda_fp16.h>
#include <cstdint>

// ---------------------------------------------------------------------------
// GATNet 2-layer GAT, N=50000, E=800000 (+self loops).
// GEMM1 = pure FP16 tensor-core GEMM (hi-only A and B, f32 accum; network
// attenuates the ~3e-4 raw GEMM rounding ~200x -> ~5e-6 final, measured).
// Messages fp16; CSR built on side stream overlapped with GEMM1.
// agg1 fuses layer-1 aggregation + bias + layer-2 GEMM + layer-2 logits.
// ---------------------------------------------------------------------------

#define NMAX 50000
#define EMAX 800000

__device__ __align__(16) __half2 g_xlh [NMAX * 32];  // xl as half2 pairs
__device__ __align__(16) float g_as1[NMAX * 8];
__device__ __align__(16) float g_ad1[NMAX * 8];
__device__ __align__(16) float g_hl2[NMAX * 16];
__device__ float g_as2[NMAX];
__device__ float g_ad2[NMAX];

__device__ int g_cnt [NMAX];   // zero at module load; re-zeroed by k_scan3
__device__ int g_inc [NMAX];
__device__ int g_bsum[64];
__device__ int g_rptr[NMAX + 1];
__device__ int g_rank[EMAX];
__device__ int g_col [EMAX];

__device__ __forceinline__ float leaky02(float a) { return fmaxf(a, 0.2f * a); }

__device__ __forceinline__ uint32_t pack2h(float x, float y) {
    __half2 hh = __floats2half2_rn(x, y);
    return *reinterpret_cast<uint32_t*>(&hh);
}

__device__ __forceinline__ void mma_f16(float4& c, uint32_t a0, uint32_t a1,
                                        uint32_t a2, uint32_t a3,
                                        uint32_t b0, uint32_t b1) {
    asm volatile(
        "mma.sync.aligned.m16n8k16.row.col.f32.f16.f16.f32 "
        "{%0,%1,%2,%3}, {%4,%5,%6,%7}, {%8,%9}, {%0,%1,%2,%3};\n"
        : "+f"(c.x), "+f"(c.y), "+f"(c.z), "+f"(c.w)
        : "r"(a0), "r"(a1), "r"(a2), "r"(a3), "r"(b0), "r"(b1));
}

// ----------------------------- CSR construction ----------------------------
__global__ void k_hist(const int* __restrict__ ei, int E) {
    int base = (blockIdx.x * blockDim.x + threadIdx.x) * 4;
    if (base >= E) return;
    int d[4];
    if (base + 4 <= E && (E & 3) == 0) {
        int4 dv = *(const int4*)(ei + E + base);
        d[0] = dv.x; d[1] = dv.y; d[2] = dv.z; d[3] = dv.w;
#pragma unroll
        for (int i = 0; i < 4; i++)
            g_rank[base + i] = atomicAdd(&g_cnt[d[i]], 1);
    } else {
        int m = E - base; if (m > 4) m = 4;
#pragma unroll
        for (int i = 0; i < 4; i++) if (i < m) d[i] = ei[E + base + i];
#pragma unroll
        for (int i = 0; i < 4; i++)
            if (i < m) g_rank[base + i] = atomicAdd(&g_cnt[d[i]], 1);
    }
}

__global__ __launch_bounds__(1024) void k_scan1(int N) {
    __shared__ int sw[32];
    int t = threadIdx.x, i = blockIdx.x * 1024 + t;
    int lane = t & 31, wid = t >> 5;
    int s = (i < N) ? g_cnt[i] : 0;
#pragma unroll
    for (int o = 1; o < 32; o <<= 1) {
        int u = __shfl_up_sync(0xffffffffu, s, o);
        if (lane >= o) s += u;
    }
    if (lane == 31) sw[wid] = s;
    __syncthreads();
    if (wid == 0) {
        int ws = sw[lane];
#pragma unroll
        for (int o = 1; o < 32; o <<= 1) {
            int u = __shfl_up_sync(0xffffffffu, ws, o);
            if (lane >= o) ws += u;
        }
        sw[lane] = ws;
    }
    __syncthreads();
    int incl = s + (wid ? sw[wid - 1] : 0);
    if (i < N) g_inc[i] = incl;
    if (t == 1023) g_bsum[blockIdx.x] = incl;
}

__global__ void k_scan3(int N, int E, int ntiles) {
    __shared__ int sh[64];
    int t = threadIdx.x;
    if (t < 32) {
        int a = (t < ntiles) ? g_bsum[t] : 0;
        int b = (t + 32 < ntiles) ? g_bsum[t + 32] : 0;
#pragma unroll
        for (int o = 1; o < 32; o <<= 1) {
            int u = __shfl_up_sync(0xffffffffu, a, o);
            if (t >= o) a += u;
        }
        int tot = __shfl_sync(0xffffffffu, a, 31);
#pragma unroll
        for (int o = 1; o < 32; o <<= 1) {
            int u = __shfl_up_sync(0xffffffffu, b, o);
            if (t >= o) b += u;
        }
        sh[t] = a;
        sh[t + 32] = b + tot;
    }
    __syncthreads();
    int i = blockIdx.x * blockDim.x + t;
    if (i < N) {
        int blk = i >> 10;
        int excl = blk ? sh[blk - 1] : 0;
        g_rptr[i] = g_inc[i] - g_cnt[i] + excl;
        g_cnt[i] = 0;   // reset for next call (dead after this point)
    }
    if (i == 0) g_rptr[N] = E;
}

__global__ void k_scatter(const int* __restrict__ ei, int E, int N) {
    int tid = blockIdx.x * blockDim.x + threadIdx.x;
    int base = tid * 4;
    if (base >= E) return;
    int d[4], s[4], r[4], rp[4];
    if (base + 4 <= E && (E & 3) == 0) {
        int4 dv = *(const int4*)(ei + E + base);
        int4 sv = *(const int4*)(ei + base);
        int4 rv = *(const int4*)(g_rank + base);
        d[0] = dv.x; d[1] = dv.y; d[2] = dv.z; d[3] = dv.w;
        s[0] = sv.x; s[1] = sv.y; s[2] = sv.z; s[3] = sv.w;
        r[0] = rv.x; r[1] = rv.y; r[2] = rv.z; r[3] = rv.w;
#pragma unroll
        for (int i = 0; i < 4; i++) rp[i] = g_rptr[d[i]];
#pragma unroll
        for (int i = 0; i < 4; i++) g_col[rp[i] + r[i]] = s[i];
    } else {
        int m = E - base; if (m > 4) m = 4;
#pragma unroll
        for (int i = 0; i < 4; i++)
            if (i < m) { d[i] = ei[E + base + i]; s[i] = ei[base + i]; }
#pragma unroll
        for (int i = 0; i < 4; i++) if (i < m) r[i] = g_rank[base + i];
#pragma unroll
        for (int i = 0; i < 4; i++) if (i < m) rp[i] = g_rptr[d[i]];
#pragma unroll
        for (int i = 0; i < 4; i++) if (i < m) g_col[rp[i] + r[i]] = s[i];
    }
}

// --------- GEMM1 (pure FP16 MMA m16n8k16) + fused node1 logits -------------
// xl = X @ W1, block tile 128x64, BK=32, 8 warps = 4(M) x 2(N), warp 32x32.
__global__ __launch_bounds__(256) void k_gemm1(const float* __restrict__ X,
                                               const float* __restrict__ W,
                                               const float* __restrict__ att_s,
                                               const float* __restrict__ att_d,
                                               int N) {
    __shared__ __align__(16) __half2 sAh2[128][20];
    __shared__ __align__(16) __half2 sBh2[16][72];

    const int tid  = threadIdx.x;
    const int bm   = blockIdx.x * 128;
    const int warp = tid >> 5, lane = tid & 31;
    const int wm   = warp >> 1, wn = warp & 1;
    const int g    = lane >> 2, tig = lane & 3;

    const int ar  = tid >> 1, af4 = (tid & 1) * 4, ah2 = (tid & 1) * 8;
    const int bkk = tid >> 4, bq = (tid & 15) * 4;

    int axr = bm + ar;
    if (axr >= N) axr = N - 1;   // clamp; stores guarded
    const float4* Xr = (const float4*)(X + (size_t)axr * 512);

    float4 acc[2][4];
#pragma unroll
    for (int i = 0; i < 2; i++)
#pragma unroll
        for (int j = 0; j < 4; j++) acc[i][j] = make_float4(0.f, 0.f, 0.f, 0.f);

    float4 ra[4], rb0, rb1;
#pragma unroll
    for (int i = 0; i < 4; i++) ra[i] = Xr[af4 + i];
    rb0 = *(const float4*)(W + (size_t)(2 * bkk) * 64 + bq);
    rb1 = *(const float4*)(W + (size_t)(2 * bkk + 1) * 64 + bq);

    for (int ks = 0; ks < 16; ks++) {
        uint32_t AH[8];
#pragma unroll
        for (int i = 0; i < 4; i++) {
            AH[2 * i]     = pack2h(ra[i].x, ra[i].y);
            AH[2 * i + 1] = pack2h(ra[i].z, ra[i].w);
        }
        *(uint4*)&sAh2[ar][ah2]     = *(uint4*)&AH[0];
        *(uint4*)&sAh2[ar][ah2 + 4] = *(uint4*)&AH[4];
        uint32_t BH[4];
        BH[0] = pack2h(rb0.x, rb1.x);
        BH[1] = pack2h(rb0.y, rb1.y);
        BH[2] = pack2h(rb0.z, rb1.z);
        BH[3] = pack2h(rb0.w, rb1.w);
        *(uint4*)&sBh2[bkk][bq] = *(uint4*)&BH[0];
        __syncthreads();

        if (ks < 15) {
            int k0 = (ks + 1) * 32;
#pragma unroll
            for (int i = 0; i < 4; i++) ra[i] = Xr[(k0 >> 2) + af4 + i];
            rb0 = *(const float4*)(W + (size_t)(k0 + 2 * bkk) * 64 + bq);
            rb1 = *(const float4*)(W + (size_t)(k0 + 2 * bkk + 1) * 64 + bq);
        }

#pragma unroll
        for (int ki = 0; ki < 2; ki++) {
            const int kc2 = ki * 8;
            uint32_t Ah[2][4];
#pragma unroll
            for (int mt = 0; mt < 2; mt++) {
                const int r0 = wm * 32 + mt * 16 + g, r8 = r0 + 8;
                Ah[mt][0] = *(const uint32_t*)&sAh2[r0][kc2 + tig];
                Ah[mt][1] = *(const uint32_t*)&sAh2[r8][kc2 + tig];
                Ah[mt][2] = *(const uint32_t*)&sAh2[r0][kc2 + tig + 4];
                Ah[mt][3] = *(const uint32_t*)&sAh2[r8][kc2 + tig + 4];
            }
#pragma unroll
            for (int nt = 0; nt < 4; nt++) {
                const int nc = wn * 32 + nt * 8 + g;
                uint32_t bh0 = *(const uint32_t*)&sBh2[kc2 + tig][nc];
                uint32_t bh1 = *(const uint32_t*)&sBh2[kc2 + tig + 4][nc];
#pragma unroll
                for (int mt = 0; mt < 2; mt++) {
                    mma_f16(acc[mt][nt], Ah[mt][0], Ah[mt][1], Ah[mt][2],
                            Ah[mt][3], bh0, bh1);
                }
            }
        }
        __syncthreads();
    }

#pragma unroll
    for (int mt = 0; mt < 2; mt++) {
        const int row0 = bm + wm * 32 + mt * 16 + g;
        const int row1 = row0 + 8;
        float s0a[4], s1a[4], d0a[4], d1a[4];
#pragma unroll
        for (int nt = 0; nt < 4; nt++) {
            const int h = wn * 4 + nt;
            const int colh = h * 4 + tig;
            float4 a = acc[mt][nt];
            if (row0 < N)
                g_xlh[(size_t)row0 * 32 + colh] = __floats2half2_rn(a.x, a.y);
            if (row1 < N)
                g_xlh[(size_t)row1 * 32 + colh] = __floats2half2_rn(a.z, a.w);

            float2 asv = make_float2(__ldg(att_s + h * 8 + 2 * tig),
                                     __ldg(att_s + h * 8 + 2 * tig + 1));
            float2 adv = make_float2(__ldg(att_d + h * 8 + 2 * tig),
                                     __ldg(att_d + h * 8 + 2 * tig + 1));
            float s0 = a.x * asv.x + a.y * asv.y;
            float s1 = a.z * asv.x + a.w * asv.y;
            float d0 = a.x * adv.x + a.y * adv.y;
            float d1 = a.z * adv.x + a.w * adv.y;
#pragma unroll
            for (int off = 1; off < 4; off <<= 1) {
                s0 += __shfl_xor_sync(0xffffffffu, s0, off);
                s1 += __shfl_xor_sync(0xffffffffu, s1, off);
                d0 += __shfl_xor_sync(0xffffffffu, d0, off);
                d1 += __shfl_xor_sync(0xffffffffu, d1, off);
            }
            s0a[nt] = s0; s1a[nt] = s1; d0a[nt] = d0; d1a[nt] = d1;
        }
        if (tig == 0) {
            if (row0 < N) {
                *(float4*)&g_as1[row0 * 8 + wn * 4] =
                    make_float4(s0a[0], s0a[1], s0a[2], s0a[3]);
                *(float4*)&g_ad1[row0 * 8 + wn * 4] =
                    make_float4(d0a[0], d0a[1], d0a[2], d0a[3]);
            }
            if (row1 < N) {
                *(float4*)&g_as1[row1 * 8 + wn * 4] =
                    make_float4(s1a[0], s1a[1], s1a[2], s1a[3]);
                *(float4*)&g_ad1[row1 * 8 + wn * 4] =
                    make_float4(d1a[0], d1a[1], d1a[2], d1a[3]);
            }
        }
    }
}

// ---- layer1 aggregation + bias + layer2 GEMM + layer2 logits (fused) ------
__global__ __launch_bounds__(256) void k_agg1(const float* __restrict__ b1,
                                              const float* __restrict__ W2,
                                              const float* __restrict__ atts2,
                                              const float* __restrict__ attd2,
                                              int N) {
    __shared__ float sh[8][64];
    int warp = (blockIdx.x * blockDim.x + threadIdx.x) >> 5;
    int wl = (threadIdx.x >> 5);
    int lane = threadIdx.x & 31;
    if (warp >= N) return;
    const int d = warp;
    const int h = lane >> 2;
    const float ad = g_ad1[d * 8 + h];

    float w = __expf(leaky02(g_as1[d * 8 + h] + ad));
    float2 v = __half22float2(g_xlh[(size_t)d * 32 + lane]);
    float nx = w * v.x, ny = w * v.y;
    float den = ((lane & 3) == 0) ? w : 0.f;

    const int e1 = g_rptr[d + 1];
#pragma unroll 4
    for (int e = g_rptr[d]; e < e1; e++) {
        int s = g_col[e];
        float we = __expf(leaky02(g_as1[s * 8 + h] + ad));
        float2 xs = __half22float2(g_xlh[(size_t)s * 32 + lane]);
        nx += we * xs.x;
        ny += we * xs.y;
        if ((lane & 3) == 0) den += we;
    }
    float dfull = __shfl_sync(0xffffffffu, den, lane & ~3) + 1e-16f;
    float inv = 1.f / dfull;

    sh[wl][lane * 2]     = nx * inv + __ldg(b1 + lane * 2);
    sh[wl][lane * 2 + 1] = ny * inv + __ldg(b1 + lane * 2 + 1);
    __syncwarp();

    const int c = lane & 15;
    const int jb = (lane >> 4) * 32;
    float y = 0.f;
#pragma unroll
    for (int j2 = 0; j2 < 32; j2++) {
        int j = jb + j2;
        y += sh[wl][j] * __ldg(W2 + j * 16 + c);
    }
    y += __shfl_xor_sync(0xffffffffu, y, 16);

    if (lane < 16) g_hl2[(size_t)d * 16 + c] = y;

    float pa = y * __ldg(atts2 + c);
    float pd = y * __ldg(attd2 + c);
#pragma unroll
    for (int off = 8; off >= 1; off >>= 1) {
        pa += __shfl_xor_sync(0xffffffffu, pa, off);
        pd += __shfl_xor_sync(0xffffffffu, pd, off);
    }
    if (lane == 0) {
        g_as2[d] = pa;
        g_ad2[d] = pd;
    }
}

// ------ layer2 aggregation + bias + elu + log_softmax (16 lanes/node) ------
__global__ __launch_bounds__(256) void k_agg2(const float* __restrict__ b2,
                                              float* __restrict__ out, int N) {
    int gid = (blockIdx.x * blockDim.x + threadIdx.x) >> 4;
    int c = threadIdx.x & 15;
    bool valid = gid < N;
    const int d = valid ? gid : 0;
    const float ad = g_ad2[d];

    float w = __expf(leaky02(g_as2[d] + ad));
    float num = w * g_hl2[(size_t)d * 16 + c];
    float den = w;

    const int e1 = g_rptr[d + 1];
#pragma unroll 4
    for (int e = g_rptr[d]; e < e1; e++) {
        int s = g_col[e];
        float we = __expf(leaky02(g_as2[s] + ad));
        num += we * g_hl2[(size_t)s * 16 + c];
        den += we;
    }
    float x = num / (den + 1e-16f) + __ldg(b2 + c);
    x = (x > 0.f) ? x : (__expf(x) - 1.f);

    float m = x;
#pragma unroll
    for (int off = 1; off < 16; off <<= 1)
        m = fmaxf(m, __shfl_xor_sync(0xffffffffu, m, off));
    float ssum = __expf(x - m);
#pragma unroll
    for (int off = 1; off < 16; off <<= 1)
        ssum += __shfl_xor_sync(0xffffffffu, ssum, off);
    if (valid) out[(size_t)d * 16 + c] = x - m - __logf(ssum);
}

// ---------------------------------------------------------------------------
extern "C" void kernel_launch(void* const* d_in, const int* in_sizes, int n_in,
                              void* d_out, int out_size) {
    const float* x     = (const float*)d_in[0];
    const int*   ei    = (const int*)d_in[1];
    const float* W1    = (const float*)d_in[2];
    const float* atts1 = (const float*)d_in[3];
    const float* attd1 = (const float*)d_in[4];
    const float* b1    = (const float*)d_in[5];
    const float* W2    = (const float*)d_in[6];
    const float* atts2 = (const float*)d_in[7];
    const float* attd2 = (const float*)d_in[8];
    const float* b2    = (const float*)d_in[9];
    float* out = (float*)d_out;

    const int N = in_sizes[0] / 512;
    const int E = in_sizes[1] / 2;
    const int ntiles = (N + 1023) >> 10;

    static cudaStream_t s_csr = nullptr;
    static cudaEvent_t ev_fork = nullptr, ev_join = nullptr;
    if (!s_csr) {
        cudaStreamCreateWithFlags(&s_csr, cudaStreamNonBlocking);
        cudaEventCreateWithFlags(&ev_fork, cudaEventDisableTiming);
        cudaEventCreateWithFlags(&ev_join, cudaEventDisableTiming);
    }

    // fork: CSR build on s_csr, GEMM1 on the main stream
    cudaEventRecord(ev_fork, 0);
    cudaStreamWaitEvent(s_csr, ev_fork, 0);

    k_hist<<<(E / 4 + 255) / 256, 256, 0, s_csr>>>(ei, E);
    k_scan1<<<ntiles, 1024, 0, s_csr>>>(N);
    k_scan3<<<(N + 255) / 256, 256, 0, s_csr>>>(N, E, ntiles);
    k_scatter<<<(E / 4 + 255) / 256, 256, 0, s_csr>>>(ei, E, N);
    cudaEventRecord(ev_join, s_csr);

    k_gemm1<<<(N + 127) / 128, 256>>>(x, W1, atts1, attd1, N);

    // join: aggregation needs both CSR and GEMM1
    cudaStreamWaitEvent(0, ev_join, 0);

    k_agg1<<<(N * 32 + 255) / 256, 256>>>(b1, W2, atts2, attd2, N);
    k_agg2<<<(N * 16 + 255) / 256, 256>>>(b2, out, N);
}

// round 17
// speedup vs baseline: 1.2144x; 1.1028x over previous
#include <cuda_runtime.h>
#include <cuda_fp16.h>
#include <cstdint>

// ---------------------------------------------------------------------------
// GATNet 2-layer GAT, N=50000, E=800000 (+self loops).
// GEMM1 = pure FP16 tensor-core GEMM (f32 accum). Messages fp16.
// CSR built on side stream overlapped with GEMM1.
// agg1: 4 nodes/warp, 8 lanes/node (lane = head) -> 4 edges retired per
// warp-iteration, no redundant exp, no in-loop shuffles (issue-bound fix).
// ---------------------------------------------------------------------------

#define NMAX 50000
#define EMAX 800000

__device__ __align__(16) __half2 g_xlh [NMAX * 32];  // xl as half2 pairs
__device__ __align__(16) float g_as1[NMAX * 8];
__device__ __align__(16) float g_ad1[NMAX * 8];
__device__ __align__(16) float g_hl2[NMAX * 16];
__device__ float g_as2[NMAX];
__device__ float g_ad2[NMAX];

__device__ int g_cnt [NMAX];   // zero at module load; re-zeroed by k_scan3
__device__ int g_inc [NMAX];
__device__ int g_bsum[64];
__device__ int g_rptr[NMAX + 1];
__device__ int g_rank[EMAX];
__device__ int g_col [EMAX];

__device__ __forceinline__ float leaky02(float a) { return fmaxf(a, 0.2f * a); }

__device__ __forceinline__ uint32_t pack2h(float x, float y) {
    __half2 hh = __floats2half2_rn(x, y);
    return *reinterpret_cast<uint32_t*>(&hh);
}

__device__ __forceinline__ void mma_f16(float4& c, uint32_t a0, uint32_t a1,
                                        uint32_t a2, uint32_t a3,
                                        uint32_t b0, uint32_t b1) {
    asm volatile(
        "mma.sync.aligned.m16n8k16.row.col.f32.f16.f16.f32 "
        "{%0,%1,%2,%3}, {%4,%5,%6,%7}, {%8,%9}, {%0,%1,%2,%3};\n"
        : "+f"(c.x), "+f"(c.y), "+f"(c.z), "+f"(c.w)
        : "r"(a0), "r"(a1), "r"(a2), "r"(a3), "r"(b0), "r"(b1));
}

// ----------------------------- CSR construction ----------------------------
__global__ void k_hist(const int* __restrict__ ei, int E) {
    int base = (blockIdx.x * blockDim.x + threadIdx.x) * 4;
    if (base >= E) return;
    int d[4];
    if (base + 4 <= E && (E & 3) == 0) {
        int4 dv = *(const int4*)(ei + E + base);
        d[0] = dv.x; d[1] = dv.y; d[2] = dv.z; d[3] = dv.w;
#pragma unroll
        for (int i = 0; i < 4; i++)
            g_rank[base + i] = atomicAdd(&g_cnt[d[i]], 1);
    } else {
        int m = E - base; if (m > 4) m = 4;
#pragma unroll
        for (int i = 0; i < 4; i++) if (i < m) d[i] = ei[E + base + i];
#pragma unroll
        for (int i = 0; i < 4; i++)
            if (i < m) g_rank[base + i] = atomicAdd(&g_cnt[d[i]], 1);
    }
}

__global__ __launch_bounds__(1024) void k_scan1(int N) {
    __shared__ int sw[32];
    int t = threadIdx.x, i = blockIdx.x * 1024 + t;
    int lane = t & 31, wid = t >> 5;
    int s = (i < N) ? g_cnt[i] : 0;
#pragma unroll
    for (int o = 1; o < 32; o <<= 1) {
        int u = __shfl_up_sync(0xffffffffu, s, o);
        if (lane >= o) s += u;
    }
    if (lane == 31) sw[wid] = s;
    __syncthreads();
    if (wid == 0) {
        int ws = sw[lane];
#pragma unroll
        for (int o = 1; o < 32; o <<= 1) {
            int u = __shfl_up_sync(0xffffffffu, ws, o);
            if (lane >= o) ws += u;
        }
        sw[lane] = ws;
    }
    __syncthreads();
    int incl = s + (wid ? sw[wid - 1] : 0);
    if (i < N) g_inc[i] = incl;
    if (t == 1023) g_bsum[blockIdx.x] = incl;
}

__global__ void k_scan3(int N, int E, int ntiles) {
    __shared__ int sh[64];
    int t = threadIdx.x;
    if (t < 32) {
        int a = (t < ntiles) ? g_bsum[t] : 0;
        int b = (t + 32 < ntiles) ? g_bsum[t + 32] : 0;
#pragma unroll
        for (int o = 1; o < 32; o <<= 1) {
            int u = __shfl_up_sync(0xffffffffu, a, o);
            if (t >= o) a += u;
        }
        int tot = __shfl_sync(0xffffffffu, a, 31);
#pragma unroll
        for (int o = 1; o < 32; o <<= 1) {
            int u = __shfl_up_sync(0xffffffffu, b, o);
            if (t >= o) b += u;
        }
        sh[t] = a;
        sh[t + 32] = b + tot;
    }
    __syncthreads();
    int i = blockIdx.x * blockDim.x + t;
    if (i < N) {
        int blk = i >> 10;
        int excl = blk ? sh[blk - 1] : 0;
        g_rptr[i] = g_inc[i] - g_cnt[i] + excl;
        g_cnt[i] = 0;   // reset for next call
    }
    if (i == 0) g_rptr[N] = E;
}

__global__ void k_scatter(const int* __restrict__ ei, int E, int N) {
    int tid = blockIdx.x * blockDim.x + threadIdx.x;
    int base = tid * 4;
    if (base >= E) return;
    int d[4], s[4], r[4], rp[4];
    if (base + 4 <= E && (E & 3) == 0) {
        int4 dv = *(const int4*)(ei + E + base);
        int4 sv = *(const int4*)(ei + base);
        int4 rv = *(const int4*)(g_rank + base);
        d[0] = dv.x; d[1] = dv.y; d[2] = dv.z; d[3] = dv.w;
        s[0] = sv.x; s[1] = sv.y; s[2] = sv.z; s[3] = sv.w;
        r[0] = rv.x; r[1] = rv.y; r[2] = rv.z; r[3] = rv.w;
#pragma unroll
        for (int i = 0; i < 4; i++) rp[i] = g_rptr[d[i]];
#pragma unroll
        for (int i = 0; i < 4; i++) g_col[rp[i] + r[i]] = s[i];
    } else {
        int m = E - base; if (m > 4) m = 4;
#pragma unroll
        for (int i = 0; i < 4; i++)
            if (i < m) { d[i] = ei[E + base + i]; s[i] = ei[base + i]; }
#pragma unroll
        for (int i = 0; i < 4; i++) if (i < m) r[i] = g_rank[base + i];
#pragma unroll
        for (int i = 0; i < 4; i++) if (i < m) rp[i] = g_rptr[d[i]];
#pragma unroll
        for (int i = 0; i < 4; i++) if (i < m) g_col[rp[i] + r[i]] = s[i];
    }
}

// --------- GEMM1 (pure FP16 MMA m16n8k16) + fused node1 logits -------------
__global__ __launch_bounds__(256) void k_gemm1(const float* __restrict__ X,
                                               const float* __restrict__ W,
                                               const float* __restrict__ att_s,
                                               const float* __restrict__ att_d,
                                               int N) {
    __shared__ __align__(16) __half2 sAh2[128][20];
    __shared__ __align__(16) __half2 sBh2[16][72];

    const int tid  = threadIdx.x;
    const int bm   = blockIdx.x * 128;
    const int warp = tid >> 5, lane = tid & 31;
    const int wm   = warp >> 1, wn = warp & 1;
    const int g    = lane >> 2, tig = lane & 3;

    const int ar  = tid >> 1, af4 = (tid & 1) * 4, ah2 = (tid & 1) * 8;
    const int bkk = tid >> 4, bq = (tid & 15) * 4;

    int axr = bm + ar;
    if (axr >= N) axr = N - 1;
    const float4* Xr = (const float4*)(X + (size_t)axr * 512);

    float4 acc[2][4];
#pragma unroll
    for (int i = 0; i < 2; i++)
#pragma unroll
        for (int j = 0; j < 4; j++) acc[i][j] = make_float4(0.f, 0.f, 0.f, 0.f);

    float4 ra[4], rb0, rb1;
#pragma unroll
    for (int i = 0; i < 4; i++) ra[i] = Xr[af4 + i];
    rb0 = *(const float4*)(W + (size_t)(2 * bkk) * 64 + bq);
    rb1 = *(const float4*)(W + (size_t)(2 * bkk + 1) * 64 + bq);

    for (int ks = 0; ks < 16; ks++) {
        uint32_t AH[8];
#pragma unroll
        for (int i = 0; i < 4; i++) {
            AH[2 * i]     = pack2h(ra[i].x, ra[i].y);
            AH[2 * i + 1] = pack2h(ra[i].z, ra[i].w);
        }
        *(uint4*)&sAh2[ar][ah2]     = *(uint4*)&AH[0];
        *(uint4*)&sAh2[ar][ah2 + 4] = *(uint4*)&AH[4];
        uint32_t BH[4];
        BH[0] = pack2h(rb0.x, rb1.x);
        BH[1] = pack2h(rb0.y, rb1.y);
        BH[2] = pack2h(rb0.z, rb1.z);
        BH[3] = pack2h(rb0.w, rb1.w);
        *(uint4*)&sBh2[bkk][bq] = *(uint4*)&BH[0];
        __syncthreads();

        if (ks < 15) {
            int k0 = (ks + 1) * 32;
#pragma unroll
            for (int i = 0; i < 4; i++) ra[i] = Xr[(k0 >> 2) + af4 + i];
            rb0 = *(const float4*)(W + (size_t)(k0 + 2 * bkk) * 64 + bq);
            rb1 = *(const float4*)(W + (size_t)(k0 + 2 * bkk + 1) * 64 + bq);
        }

#pragma unroll
        for (int ki = 0; ki < 2; ki++) {
            const int kc2 = ki * 8;
            uint32_t Ah[2][4];
#pragma unroll
            for (int mt = 0; mt < 2; mt++) {
                const int r0 = wm * 32 + mt * 16 + g, r8 = r0 + 8;
                Ah[mt][0] = *(const uint32_t*)&sAh2[r0][kc2 + tig];
                Ah[mt][1] = *(const uint32_t*)&sAh2[r8][kc2 + tig];
                Ah[mt][2] = *(const uint32_t*)&sAh2[r0][kc2 + tig + 4];
                Ah[mt][3] = *(const uint32_t*)&sAh2[r8][kc2 + tig + 4];
            }
#pragma unroll
            for (int nt = 0; nt < 4; nt++) {
                const int nc = wn * 32 + nt * 8 + g;
                uint32_t bh0 = *(const uint32_t*)&sBh2[kc2 + tig][nc];
                uint32_t bh1 = *(const uint32_t*)&sBh2[kc2 + tig + 4][nc];
#pragma unroll
                for (int mt = 0; mt < 2; mt++) {
                    mma_f16(acc[mt][nt], Ah[mt][0], Ah[mt][1], Ah[mt][2],
                            Ah[mt][3], bh0, bh1);
                }
            }
        }
        __syncthreads();
    }

#pragma unroll
    for (int mt = 0; mt < 2; mt++) {
        const int row0 = bm + wm * 32 + mt * 16 + g;
        const int row1 = row0 + 8;
        float s0a[4], s1a[4], d0a[4], d1a[4];
#pragma unroll
        for (int nt = 0; nt < 4; nt++) {
            const int h = wn * 4 + nt;
            const int colh = h * 4 + tig;
            float4 a = acc[mt][nt];
            if (row0 < N)
                g_xlh[(size_t)row0 * 32 + colh] = __floats2half2_rn(a.x, a.y);
            if (row1 < N)
                g_xlh[(size_t)row1 * 32 + colh] = __floats2half2_rn(a.z, a.w);

            float2 asv = make_float2(__ldg(att_s + h * 8 + 2 * tig),
                                     __ldg(att_s + h * 8 + 2 * tig + 1));
            float2 adv = make_float2(__ldg(att_d + h * 8 + 2 * tig),
                                     __ldg(att_d + h * 8 + 2 * tig + 1));
            float s0 = a.x * asv.x + a.y * asv.y;
            float s1 = a.z * asv.x + a.w * asv.y;
            float d0 = a.x * adv.x + a.y * adv.y;
            float d1 = a.z * adv.x + a.w * adv.y;
#pragma unroll
            for (int off = 1; off < 4; off <<= 1) {
                s0 += __shfl_xor_sync(0xffffffffu, s0, off);
                s1 += __shfl_xor_sync(0xffffffffu, s1, off);
                d0 += __shfl_xor_sync(0xffffffffu, d0, off);
                d1 += __shfl_xor_sync(0xffffffffu, d1, off);
            }
            s0a[nt] = s0; s1a[nt] = s1; d0a[nt] = d0; d1a[nt] = d1;
        }
        if (tig == 0) {
            if (row0 < N) {
                *(float4*)&g_as1[row0 * 8 + wn * 4] =
                    make_float4(s0a[0], s0a[1], s0a[2], s0a[3]);
                *(float4*)&g_ad1[row0 * 8 + wn * 4] =
                    make_float4(d0a[0], d0a[1], d0a[2], d0a[3]);
            }
            if (row1 < N) {
                *(float4*)&g_as1[row1 * 8 + wn * 4] =
                    make_float4(s1a[0], s1a[1], s1a[2], s1a[3]);
                *(float4*)&g_ad1[row1 * 8 + wn * 4] =
                    make_float4(d1a[0], d1a[1], d1a[2], d1a[3]);
            }
        }
    }
}

// ---- layer1 aggregation: 4 nodes/warp, 8 lanes/node (lane = head) ---------
// + bias + layer2 GEMM + layer2 logits fused. Block 256 = 8 warps = 32 nodes.
__global__ __launch_bounds__(256) void k_agg1(const float* __restrict__ b1,
                                              const float* __restrict__ W2,
                                              const float* __restrict__ atts2,
                                              const float* __restrict__ attd2,
                                              int N) {
    __shared__ float sh[32][64];
    const int lane = threadIdx.x & 31;
    const int warpInBlk = threadIdx.x >> 5;
    const int warpG = blockIdx.x * 8 + warpInBlk;
    const int q = lane >> 3;          // node slot 0..3
    const int h = lane & 7;           // head owned by this lane
    int node = warpG * 4 + q;
    const bool valid = node < N;
    const int d = valid ? node : N - 1;

    const float ad = g_ad1[d * 8 + h];

    // self loop
    float w = __expf(leaky02(g_as1[d * 8 + h] + ad));
    float acc[8];
    {
        uint4 xv = *(const uint4*)&g_xlh[(size_t)d * 32 + h * 4];
        const __half2* xh = (const __half2*)&xv;
#pragma unroll
        for (int t = 0; t < 4; t++) {
            float2 f = __half22float2(xh[t]);
            acc[2 * t]     = w * f.x;
            acc[2 * t + 1] = w * f.y;
        }
    }
    float den = w;

    const int r0 = g_rptr[d];
    const int len = g_rptr[d + 1] - r0;
    // warp-wide max length
    int maxlen = len;
#pragma unroll
    for (int off = 16; off >= 1; off >>= 1)
        maxlen = max(maxlen, __shfl_xor_sync(0xffffffffu, maxlen, off));

    for (int i = 0; i < maxlen; i++) {
        bool act = i < len;
        int s = d;
        if (act) s = g_col[r0 + i];
        float a = g_as1[s * 8 + h];
        uint4 xv = *(const uint4*)&g_xlh[(size_t)s * 32 + h * 4];
        float we = act ? __expf(leaky02(a + ad)) : 0.f;
        const __half2* xh = (const __half2*)&xv;
#pragma unroll
        for (int t = 0; t < 4; t++) {
            float2 f = __half22float2(xh[t]);
            acc[2 * t]     += we * f.x;
            acc[2 * t + 1] += we * f.y;
        }
        den += we;
    }

    // normalize + bias -> smem h row
    float inv = 1.f / (den + 1e-16f);
    const int row = warpInBlk * 4 + q;
#pragma unroll
    for (int t = 0; t < 4; t++) {
        sh[row][h * 8 + 2 * t]     = acc[2 * t] * inv + __ldg(b1 + h * 8 + 2 * t);
        sh[row][h * 8 + 2 * t + 1] = acc[2 * t + 1] * inv + __ldg(b1 + h * 8 + 2 * t + 1);
    }
    __syncwarp();

    // layer2 GEMM + logits: 2 passes, 16 lanes per node
    const int c = lane & 15;
#pragma unroll
    for (int p = 0; p < 2; p++) {
        const int qq = (lane >> 4) + 2 * p;
        const int dd = warpG * 4 + qq;
        const float* hrow = sh[warpInBlk * 4 + qq];
        float y = 0.f;
#pragma unroll
        for (int j = 0; j < 64; j++)
            y += hrow[j] * __ldg(W2 + j * 16 + c);
        if (dd < N) g_hl2[(size_t)dd * 16 + c] = y;

        float pa = y * __ldg(atts2 + c);
        float pd = y * __ldg(attd2 + c);
#pragma unroll
        for (int off = 8; off >= 1; off >>= 1) {
            pa += __shfl_xor_sync(0xffffffffu, pa, off);
            pd += __shfl_xor_sync(0xffffffffu, pd, off);
        }
        if (c == 0 && dd < N) {
            g_as2[dd] = pa;
            g_ad2[dd] = pd;
        }
    }
}

// ------ layer2 aggregation + bias + elu + log_softmax (16 lanes/node) ------
__global__ __launch_bounds__(256) void k_agg2(const float* __restrict__ b2,
                                              float* __restrict__ out, int N) {
    int gid = (blockIdx.x * blockDim.x + threadIdx.x) >> 4;
    int c = threadIdx.x & 15;
    bool valid = gid < N;
    const int d = valid ? gid : 0;
    const float ad = g_ad2[d];

    float w = __expf(leaky02(g_as2[d] + ad));
    float num = w * g_hl2[(size_t)d * 16 + c];
    float den = w;

    const int e1 = g_rptr[d + 1];
#pragma unroll 4
    for (int e = g_rptr[d]; e < e1; e++) {
        int s = g_col[e];
        float we = __expf(leaky02(g_as2[s] + ad));
        num += we * g_hl2[(size_t)s * 16 + c];
        den += we;
    }
    float x = num / (den + 1e-16f) + __ldg(b2 + c);
    x = (x > 0.f) ? x : (__expf(x) - 1.f);

    float m = x;
#pragma unroll
    for (int off = 1; off < 16; off <<= 1)
        m = fmaxf(m, __shfl_xor_sync(0xffffffffu, m, off));
    float ssum = __expf(x - m);
#pragma unroll
    for (int off = 1; off < 16; off <<= 1)
        ssum += __shfl_xor_sync(0xffffffffu, ssum, off);
    if (valid) out[(size_t)d * 16 + c] = x - m - __logf(ssum);
}

// ---------------------------------------------------------------------------
extern "C" void kernel_launch(void* const* d_in, const int* in_sizes, int n_in,
                              void* d_out, int out_size) {
    const float* x     = (const float*)d_in[0];
    const int*   ei    = (const int*)d_in[1];
    const float* W1    = (const float*)d_in[2];
    const float* atts1 = (const float*)d_in[3];
    const float* attd1 = (const float*)d_in[4];
    const float* b1    = (const float*)d_in[5];
    const float* W2    = (const float*)d_in[6];
    const float* atts2 = (const float*)d_in[7];
    const float* attd2 = (const float*)d_in[8];
    const float* b2    = (const float*)d_in[9];
    float* out = (float*)d_out;

    const int N = in_sizes[0] / 512;
    const int E = in_sizes[1] / 2;
    const int ntiles = (N + 1023) >> 10;

    static cudaStream_t s_csr = nullptr;
    static cudaEvent_t ev_fork = nullptr, ev_join = nullptr;
    if (!s_csr) {
        cudaStreamCreateWithFlags(&s_csr, cudaStreamNonBlocking);
        cudaEventCreateWithFlags(&ev_fork, cudaEventDisableTiming);
        cudaEventCreateWithFlags(&ev_join, cudaEventDisableTiming);
    }

    // fork: CSR build on s_csr, GEMM1 on the main stream
    cudaEventRecord(ev_fork, 0);
    cudaStreamWaitEvent(s_csr, ev_fork, 0);

    k_hist<<<(E / 4 + 255) / 256, 256, 0, s_csr>>>(ei, E);
    k_scan1<<<ntiles, 1024, 0, s_csr>>>(N);
    k_scan3<<<(N + 255) / 256, 256, 0, s_csr>>>(N, E, ntiles);
    k_scatter<<<(E / 4 + 255) / 256, 256, 0, s_csr>>>(ei, E, N);
    cudaEventRecord(ev_join, s_csr);

    k_gemm1<<<(N + 127) / 128, 256>>>(x, W1, atts1, attd1, N);

    // join: aggregation needs both CSR and GEMM1
    cudaStreamWaitEvent(0, ev_join, 0);

    // 32 nodes per 256-thread block (4 nodes/warp)
    k_agg1<<<(N + 31) / 32, 256>>>(b1, W2, atts2, attd2, N);
    k_agg2<<<(N * 16 + 255) / 256, 256>>>(b2, out, N);
}